// round 3
// baseline (speedup 1.0000x reference)
#include <cuda_runtime.h>
#include <cstdint>

#define FULLMASK 0xffffffffu
#define BB 4096
#define TT 200
#define FF 16
#define H1 55
#define H1P 56
#define H2 30
#define H2P 32
#define NWARP 7
#define NTHR (NWARP * 32)
#define EPW 4

// shared layout in float4 units
#define OFF_WX1 0
#define OFF_WH1 (OFF_WX1 + FF * H1P)      // 896
#define OFF_B1  (OFF_WH1 + H1 * H1P)      // 3976
#define OFF_WI2 (OFF_B1 + H1P)            // 4032
#define OFF_WH2 (OFF_WI2 + H1 * H2P)      // 5792
#define OFF_B2  (OFF_WH2 + H2 * H2P)      // 6752
#define N_F4    (OFF_B2 + H2P)            // 6784
#define OFF_WFC (N_F4 * 4)                // float index
#define OFF_BFC (OFF_WFC + 6 * H2P)
#define SMEM_BYTES ((OFF_BFC + 8) * 4)

// NOTE: parameter names must not collide with float4 member tokens x/y/z/w
#define FMA4(ACC_, WV_, SV_) do { \
    (ACC_).x = fmaf((WV_).x, (SV_), (ACC_).x); \
    (ACC_).y = fmaf((WV_).y, (SV_), (ACC_).y); \
    (ACC_).z = fmaf((WV_).z, (SV_), (ACC_).z); \
    (ACC_).w = fmaf((WV_).w, (SV_), (ACC_).w); } while (0)

static __device__ __forceinline__ float sigf(float v) {
    return __fdividef(1.0f, 1.0f + __expf(-v));
}
static __device__ __forceinline__ float tanhf_fast(float v) {
    return __fdividef(2.0f, 1.0f + __expf(-2.0f * v)) - 1.0f;
}

// stage W[4H,K] -> dst[k*pad + u] = float4{gates i,f,g,o of unit u at input k}
static __device__ void stageW(float4* dst, const float* W, int H, int K, int pad, int tid) {
    for (int i = tid; i < K * pad; i += NTHR) {
        int k = i / pad, u = i % pad;
        float4 v = make_float4(0.f, 0.f, 0.f, 0.f);
        if (u < H) {
            v.x = W[(0 * H + u) * K + k];
            v.y = W[(1 * H + u) * K + k];
            v.z = W[(2 * H + u) * K + k];
            v.w = W[(3 * H + u) * K + k];
        }
        dst[i] = v;
    }
}
static __device__ void stageB(float4* dst, const float* b1, const float* b2, int H, int pad, int tid) {
    for (int u = tid; u < pad; u += NTHR) {
        float4 v = make_float4(0.f, 0.f, 0.f, 0.f);
        if (u < H) {
            v.x = b1[0 * H + u] + b2[0 * H + u];
            v.y = b1[1 * H + u] + b2[1 * H + u];
            v.z = b1[2 * H + u] + b2[2 * H + u];
            v.w = b1[3 * H + u] + b2[3 * H + u];
        }
        dst[u] = v;
    }
}

__global__ void __launch_bounds__(NTHR, 1)
lstm2_kernel(const float* __restrict__ x,
             const float* __restrict__ Wih1, const float* __restrict__ Whh1,
             const float* __restrict__ bih1, const float* __restrict__ bhh1,
             const float* __restrict__ Wih2, const float* __restrict__ Whh2,
             const float* __restrict__ bih2, const float* __restrict__ bhh2,
             const float* __restrict__ Wfc,  const float* __restrict__ bfc,
             float* __restrict__ out)
{
    extern __shared__ float4 sm4[];
    float* smf = (float*)sm4;
    const int tid = threadIdx.x;

    stageW(sm4 + OFF_WX1, Wih1, H1, FF, H1P, tid);
    stageW(sm4 + OFF_WH1, Whh1, H1, H1, H1P, tid);
    stageB(sm4 + OFF_B1, bih1, bhh1, H1, H1P, tid);
    stageW(sm4 + OFF_WI2, Wih2, H2, H1, H2P, tid);
    stageW(sm4 + OFF_WH2, Whh2, H2, H2, H2P, tid);
    stageB(sm4 + OFF_B2, bih2, bhh2, H2, H2P, tid);
    for (int i = tid; i < 6 * H2P; i += NTHR) {
        int m = i / H2P, l = i % H2P;
        smf[OFF_WFC + i] = (l < H2) ? Wfc[m * H2 + l] : 0.f;
    }
    if (tid < 6) smf[OFF_BFC + tid] = bfc[tid];
    __syncthreads();

    const int lane = tid & 31;
    const int w = tid >> 5;
    const int ebase = (blockIdx.x * NWARP + w) * EPW;
    if (ebase >= BB) return;

    const int uA = lane;
    const int uB = (32 + lane < H1) ? (32 + lane) : H1;  // lanes >=23 -> zero-pad unit

    const float4 b1A = sm4[OFF_B1 + uA];
    const float4 b1B = sm4[OFF_B1 + uB];
    const float4 b2v = sm4[OFF_B2 + lane];

    const int half = lane >> 4;
    const int feat = lane & 15;
    const float* xp0 = x + (size_t)(ebase + half) * TT * FF + feat;      // elems 0,1
    const float* xp1 = x + (size_t)(ebase + 2 + half) * TT * FF + feat;  // elems 2,3

    float h1lo[EPW], h1hi[EPW], c1lo[EPW], c1hi[EPW], h2v[EPW], c2v[EPW];
#pragma unroll
    for (int e = 0; e < EPW; ++e)
        h1lo[e] = h1hi[e] = c1lo[e] = c1hi[e] = h2v[e] = c2v[e] = 0.f;

    float xa = __ldg(xp0);
    float xb = __ldg(xp1);

    for (int t = 0; t < TT; ++t) {
        const int tn = (t + 1 < TT) ? (t + 1) : t;
        const float xa_n = __ldg(xp0 + (size_t)tn * FF);
        const float xb_n = __ldg(xp1 + (size_t)tn * FF);

        // ---- layer 1 gate accumulation ----
        float4 aA[EPW], aB[EPW];
#pragma unroll
        for (int e = 0; e < EPW; ++e) { aA[e] = b1A; aB[e] = b1B; }

#pragma unroll
        for (int k = 0; k < FF; ++k) {
            const float4 wA = sm4[OFF_WX1 + k * H1P + uA];
            const float4 wB = sm4[OFF_WX1 + k * H1P + uB];
            float xk[EPW];
            xk[0] = __shfl_sync(FULLMASK, xa, k);
            xk[1] = __shfl_sync(FULLMASK, xa, 16 + k);
            xk[2] = __shfl_sync(FULLMASK, xb, k);
            xk[3] = __shfl_sync(FULLMASK, xb, 16 + k);
#pragma unroll
            for (int e = 0; e < EPW; ++e) { FMA4(aA[e], wA, xk[e]); FMA4(aB[e], wB, xk[e]); }
        }
#pragma unroll 4
        for (int k = 0; k < 32; ++k) {
            const float4 wA = sm4[OFF_WH1 + k * H1P + uA];
            const float4 wB = sm4[OFF_WH1 + k * H1P + uB];
#pragma unroll
            for (int e = 0; e < EPW; ++e) {
                const float hk = __shfl_sync(FULLMASK, h1lo[e], k);
                FMA4(aA[e], wA, hk); FMA4(aB[e], wB, hk);
            }
        }
#pragma unroll 4
        for (int k = 32; k < H1; ++k) {
            const float4 wA = sm4[OFF_WH1 + k * H1P + uA];
            const float4 wB = sm4[OFF_WH1 + k * H1P + uB];
#pragma unroll
            for (int e = 0; e < EPW; ++e) {
                const float hk = __shfl_sync(FULLMASK, h1hi[e], k - 32);
                FMA4(aA[e], wA, hk); FMA4(aB[e], wB, hk);
            }
        }

        float nh1lo[EPW], nh1hi[EPW];
#pragma unroll
        for (int e = 0; e < EPW; ++e) {
            float ig = sigf(aA[e].x), fg = sigf(aA[e].y);
            float gg = tanhf_fast(aA[e].z), og = sigf(aA[e].w);
            c1lo[e] = fg * c1lo[e] + ig * gg;
            nh1lo[e] = og * tanhf_fast(c1lo[e]);
            ig = sigf(aB[e].x); fg = sigf(aB[e].y);
            gg = tanhf_fast(aB[e].z); og = sigf(aB[e].w);
            c1hi[e] = fg * c1hi[e] + ig * gg;
            nh1hi[e] = og * tanhf_fast(c1hi[e]);
        }
#pragma unroll
        for (int e = 0; e < EPW; ++e) { h1lo[e] = nh1lo[e]; h1hi[e] = nh1hi[e]; }

        // ---- layer 2 gate accumulation ----
        float4 a2[EPW];
#pragma unroll
        for (int e = 0; e < EPW; ++e) a2[e] = b2v;

#pragma unroll 4
        for (int k = 0; k < 32; ++k) {
            const float4 w2 = sm4[OFF_WI2 + k * H2P + lane];
#pragma unroll
            for (int e = 0; e < EPW; ++e) {
                const float hk = __shfl_sync(FULLMASK, h1lo[e], k);
                FMA4(a2[e], w2, hk);
            }
        }
#pragma unroll 4
        for (int k = 32; k < H1; ++k) {
            const float4 w2 = sm4[OFF_WI2 + k * H2P + lane];
#pragma unroll
            for (int e = 0; e < EPW; ++e) {
                const float hk = __shfl_sync(FULLMASK, h1hi[e], k - 32);
                FMA4(a2[e], w2, hk);
            }
        }
#pragma unroll 4
        for (int k = 0; k < H2; ++k) {
            const float4 w2 = sm4[OFF_WH2 + k * H2P + lane];
#pragma unroll
            for (int e = 0; e < EPW; ++e) {
                const float hk = __shfl_sync(FULLMASK, h2v[e], k);
                FMA4(a2[e], w2, hk);
            }
        }
#pragma unroll
        for (int e = 0; e < EPW; ++e) {
            float ig = sigf(a2[e].x), fg = sigf(a2[e].y);
            float gg = tanhf_fast(a2[e].z), og = sigf(a2[e].w);
            c2v[e] = fg * c2v[e] + ig * gg;
            h2v[e] = og * tanhf_fast(c2v[e]);
        }

        xa = xa_n;
        xb = xb_n;
    }

    // ---- final FC: out[e][m] = sum_l Wfc[m][l] * h2[e][l] + bfc[m] ----
#pragma unroll
    for (int e = 0; e < EPW; ++e) {
#pragma unroll
        for (int m = 0; m < 6; ++m) {
            float p = smf[OFF_WFC + m * H2P + lane] * h2v[e];
#pragma unroll
            for (int off = 16; off > 0; off >>= 1)
                p += __shfl_xor_sync(FULLMASK, p, off);
            if (lane == 0)
                out[(size_t)(ebase + e) * 6 + m] = p + smf[OFF_BFC + m];
        }
    }
}

extern "C" void kernel_launch(void* const* d_in, const int* in_sizes, int n_in,
                              void* d_out, int out_size) {
    (void)in_sizes; (void)n_in; (void)out_size;
    const float* x    = (const float*)d_in[0];
    const float* Wih1 = (const float*)d_in[1];
    const float* Whh1 = (const float*)d_in[2];
    const float* bih1 = (const float*)d_in[3];
    const float* bhh1 = (const float*)d_in[4];
    const float* Wih2 = (const float*)d_in[5];
    const float* Whh2 = (const float*)d_in[6];
    const float* bih2 = (const float*)d_in[7];
    const float* bhh2 = (const float*)d_in[8];
    const float* Wfc  = (const float*)d_in[9];
    const float* bfc  = (const float*)d_in[10];
    float* out = (float*)d_out;

    static bool attr_set = false;
    if (!attr_set) {
        cudaFuncSetAttribute(lstm2_kernel,
                             cudaFuncAttributeMaxDynamicSharedMemorySize, SMEM_BYTES);
        attr_set = true;
    }
    const int epc = NWARP * EPW;               // 28 elements per CTA
    const int grid = (BB + epc - 1) / epc;     // 147
    lstm2_kernel<<<grid, NTHR, SMEM_BYTES>>>(x, Wih1, Whh1, bih1, bhh1,
                                             Wih2, Whh2, bih2, bhh2, Wfc, bfc, out);
}

// round 4
// speedup vs baseline: 1.2697x; 1.2697x over previous
#include <cuda_runtime.h>
#include <cstdint>

#define FULLMASK 0xffffffffu
#define BB 4096
#define TT 200
#define FF 16
#define H1 55
#define H1P 56
#define H2 30
#define H2P 32
#define NWARP 7
#define NTHR (NWARP * 32)
#define EPW 4

typedef unsigned long long u64;

// ---- shared layout in float4 units ----
#define OFF_WX1 0
#define OFF_WH1 (OFF_WX1 + FF * H1P)       // 896
#define OFF_B1  (OFF_WH1 + H1 * H1P)       // 3976
#define OFF_WI2 (OFF_B1 + H1P)             // 4032
#define OFF_WH2 (OFF_WI2 + H1 * H2P)       // 5792
#define OFF_B2  (OFF_WH2 + H2 * H2P)       // 6752
#define OFF_HS  (OFF_B2 + H2P)             // 6784 : per-warp h strips
#define HS_PER_WARP (H1P + H2P)            // 88
#define N_F4_ALL (OFF_HS + NWARP * HS_PER_WARP)  // 7400
#define OFF_WFC (N_F4_ALL * 4)             // float index
#define OFF_BFC (OFF_WFC + 6 * H2P)
#define SMEM_BYTES ((OFF_BFC + 8) * 4)     // ~119 KB

static __device__ __forceinline__ u64 pk2(float lo, float hi) {
    u64 r; asm("mov.b64 %0, {%1, %2};" : "=l"(r) : "f"(lo), "f"(hi)); return r;
}
static __device__ __forceinline__ void unpk(u64 v, float& lo, float& hi) {
    asm("mov.b64 {%0, %1}, %2;" : "=f"(lo), "=f"(hi) : "l"(v));
}
static __device__ __forceinline__ void fma2(u64& acc, u64 a, u64 b) {
    asm("fma.rn.f32x2 %0, %1, %2, %0;" : "+l"(acc) : "l"(a), "l"(b));
}

static __device__ __forceinline__ float sigf(float v) {
    return __fdividef(1.0f, 1.0f + __expf(-v));
}
static __device__ __forceinline__ float tanhf_fast(float v) {
    return __fdividef(2.0f, 1.0f + __expf(-2.0f * v)) - 1.0f;
}

// stage W[4H,K] -> dst[k*pad + u] = float4{gates i,f,g,o of unit u at input k}
static __device__ void stageW(float4* dst, const float* W, int H, int K, int pad, int tid) {
    for (int i = tid; i < K * pad; i += NTHR) {
        int k = i / pad, u = i % pad;
        float4 v = make_float4(0.f, 0.f, 0.f, 0.f);
        if (u < H) {
            v.x = W[(0 * H + u) * K + k];
            v.y = W[(1 * H + u) * K + k];
            v.z = W[(2 * H + u) * K + k];
            v.w = W[(3 * H + u) * K + k];
        }
        dst[i] = v;
    }
}
static __device__ void stageB(float4* dst, const float* b1, const float* b2, int H, int pad, int tid) {
    for (int u = tid; u < pad; u += NTHR) {
        float4 v = make_float4(0.f, 0.f, 0.f, 0.f);
        if (u < H) {
            v.x = b1[0 * H + u] + b2[0 * H + u];
            v.y = b1[1 * H + u] + b2[1 * H + u];
            v.z = b1[2 * H + u] + b2[2 * H + u];
            v.w = b1[3 * H + u] + b2[3 * H + u];
        }
        dst[u] = v;
    }
}

__global__ void __launch_bounds__(NTHR, 1)
lstm2_kernel(const float* __restrict__ x,
             const float* __restrict__ Wih1, const float* __restrict__ Whh1,
             const float* __restrict__ bih1, const float* __restrict__ bhh1,
             const float* __restrict__ Wih2, const float* __restrict__ Whh2,
             const float* __restrict__ bih2, const float* __restrict__ bhh2,
             const float* __restrict__ Wfc,  const float* __restrict__ bfc,
             float* __restrict__ out)
{
    extern __shared__ float4 sm4[];
    float* smf = (float*)sm4;
    const int tid = threadIdx.x;

    stageW(sm4 + OFF_WX1, Wih1, H1, FF, H1P, tid);
    stageW(sm4 + OFF_WH1, Whh1, H1, H1, H1P, tid);
    stageB(sm4 + OFF_B1, bih1, bhh1, H1, H1P, tid);
    stageW(sm4 + OFF_WI2, Wih2, H2, H1, H2P, tid);
    stageW(sm4 + OFF_WH2, Whh2, H2, H2, H2P, tid);
    stageB(sm4 + OFF_B2, bih2, bhh2, H2, H2P, tid);
    for (int i = tid; i < NWARP * HS_PER_WARP; i += NTHR)
        sm4[OFF_HS + i] = make_float4(0.f, 0.f, 0.f, 0.f);
    for (int i = tid; i < 6 * H2P; i += NTHR) {
        int m = i / H2P, l = i % H2P;
        smf[OFF_WFC + i] = (l < H2) ? Wfc[m * H2 + l] : 0.f;
    }
    if (tid < 6) smf[OFF_BFC + tid] = bfc[tid];
    __syncthreads();

    const int lane = tid & 31;
    const int w = tid >> 5;
    const int ebase = (blockIdx.x * NWARP + w) * EPW;
    if (ebase >= BB) return;

    const int uA = lane;
    const int uB = (32 + lane < H1) ? (32 + lane) : H1;  // lanes >= 23 hit zero-pad unit 55

    float4* h1s = sm4 + OFF_HS + w * HS_PER_WARP;   // [56] float4 {e0..e3}
    float4* h2s = h1s + H1P;                         // [32]

    // packed biases
    const float4 b1A = sm4[OFF_B1 + uA];
    const float4 b1B = sm4[OFF_B1 + uB];
    const float4 b2v = sm4[OFF_B2 + lane];
    const u64 b1A_if = pk2(b1A.x, b1A.y), b1A_go = pk2(b1A.z, b1A.w);
    const u64 b1B_if = pk2(b1B.x, b1B.y), b1B_go = pk2(b1B.z, b1B.w);
    const u64 b2_if  = pk2(b2v.x, b2v.y), b2_go  = pk2(b2v.z, b2v.w);

    const int half = lane >> 4;
    const int feat = lane & 15;
    const float* xp0 = x + (size_t)(ebase + half) * TT * FF + feat;      // elems 0,1
    const float* xp1 = x + (size_t)(ebase + 2 + half) * TT * FF + feat;  // elems 2,3

    float c1lo[EPW], c1hi[EPW], c2v[EPW], h2v[EPW];
#pragma unroll
    for (int e = 0; e < EPW; ++e) c1lo[e] = c1hi[e] = c2v[e] = h2v[e] = 0.f;

    float xa = __ldg(xp0);
    float xb = __ldg(xp1);

    for (int t = 0; t < TT; ++t) {
        const int tn = (t + 1 < TT) ? (t + 1) : t;
        const float xa_n = __ldg(xp0 + (size_t)tn * FF);
        const float xb_n = __ldg(xp1 + (size_t)tn * FF);

        // ---------- layer 1 ----------
        u64 aAif[EPW], aAgo[EPW], aBif[EPW], aBgo[EPW];
#pragma unroll
        for (int e = 0; e < EPW; ++e) {
            aAif[e] = b1A_if; aAgo[e] = b1A_go;
            aBif[e] = b1B_if; aBgo[e] = b1B_go;
        }

        // input projection (x via shuffles)
#pragma unroll
        for (int k = 0; k < FF; ++k) {
            const ulonglong2 wA = *(const ulonglong2*)(sm4 + OFF_WX1 + k * H1P + uA);
            const ulonglong2 wB = *(const ulonglong2*)(sm4 + OFF_WX1 + k * H1P + uB);
            float xk[EPW];
            xk[0] = __shfl_sync(FULLMASK, xa, k);
            xk[1] = __shfl_sync(FULLMASK, xa, 16 + k);
            xk[2] = __shfl_sync(FULLMASK, xb, k);
            xk[3] = __shfl_sync(FULLMASK, xb, 16 + k);
#pragma unroll
            for (int e = 0; e < EPW; ++e) {
                const u64 px = pk2(xk[e], xk[e]);
                fma2(aAif[e], wA.x, px); fma2(aAgo[e], wA.y, px);
                fma2(aBif[e], wB.x, px); fma2(aBgo[e], wB.y, px);
            }
        }
        // recurrent projection (h via broadcast LDS.128)
#pragma unroll 5
        for (int k = 0; k < H1; ++k) {
            const ulonglong2 wA = *(const ulonglong2*)(sm4 + OFF_WH1 + k * H1P + uA);
            const ulonglong2 wB = *(const ulonglong2*)(sm4 + OFF_WH1 + k * H1P + uB);
            const float4 hv = h1s[k];
            const float hvv[EPW] = {hv.x, hv.y, hv.z, hv.w};
#pragma unroll
            for (int e = 0; e < EPW; ++e) {
                const u64 ph = pk2(hvv[e], hvv[e]);
                fma2(aAif[e], wA.x, ph); fma2(aAgo[e], wA.y, ph);
                fma2(aBif[e], wB.x, ph); fma2(aBgo[e], wB.y, ph);
            }
        }

        float nh1lo[EPW], nh1hi[EPW];
#pragma unroll
        for (int e = 0; e < EPW; ++e) {
            float ig, fg, gg, og;
            unpk(aAif[e], ig, fg); unpk(aAgo[e], gg, og);
            ig = sigf(ig); fg = sigf(fg); gg = tanhf_fast(gg); og = sigf(og);
            c1lo[e] = fg * c1lo[e] + ig * gg;
            nh1lo[e] = og * tanhf_fast(c1lo[e]);
            unpk(aBif[e], ig, fg); unpk(aBgo[e], gg, og);
            ig = sigf(ig); fg = sigf(fg); gg = tanhf_fast(gg); og = sigf(og);
            c1hi[e] = fg * c1hi[e] + ig * gg;
            nh1hi[e] = og * tanhf_fast(c1hi[e]);
        }
        h1s[uA] = make_float4(nh1lo[0], nh1lo[1], nh1lo[2], nh1lo[3]);
        h1s[uB] = make_float4(nh1hi[0], nh1hi[1], nh1hi[2], nh1hi[3]);  // pad unit 55: zeros
        __syncwarp();

        // ---------- layer 2 ----------
        u64 a2if[EPW], a2go[EPW];
#pragma unroll
        for (int e = 0; e < EPW; ++e) { a2if[e] = b2_if; a2go[e] = b2_go; }

#pragma unroll 5
        for (int k = 0; k < H1; ++k) {
            const ulonglong2 w2 = *(const ulonglong2*)(sm4 + OFF_WI2 + k * H2P + lane);
            const float4 hv = h1s[k];
            const float hvv[EPW] = {hv.x, hv.y, hv.z, hv.w};
#pragma unroll
            for (int e = 0; e < EPW; ++e) {
                const u64 ph = pk2(hvv[e], hvv[e]);
                fma2(a2if[e], w2.x, ph); fma2(a2go[e], w2.y, ph);
            }
        }
#pragma unroll 5
        for (int k = 0; k < H2; ++k) {
            const ulonglong2 w2 = *(const ulonglong2*)(sm4 + OFF_WH2 + k * H2P + lane);
            const float4 hv = h2s[k];
            const float hvv[EPW] = {hv.x, hv.y, hv.z, hv.w};
#pragma unroll
            for (int e = 0; e < EPW; ++e) {
                const u64 ph = pk2(hvv[e], hvv[e]);
                fma2(a2if[e], w2.x, ph); fma2(a2go[e], w2.y, ph);
            }
        }
#pragma unroll
        for (int e = 0; e < EPW; ++e) {
            float ig, fg, gg, og;
            unpk(a2if[e], ig, fg); unpk(a2go[e], gg, og);
            ig = sigf(ig); fg = sigf(fg); gg = tanhf_fast(gg); og = sigf(og);
            c2v[e] = fg * c2v[e] + ig * gg;
            h2v[e] = og * tanhf_fast(c2v[e]);
        }
        h2s[lane] = make_float4(h2v[0], h2v[1], h2v[2], h2v[3]);  // lanes 30,31: zeros
        __syncwarp();

        xa = xa_n;
        xb = xb_n;
    }

    // ---- final FC: out[e][m] = sum_l Wfc[m][l] * h2[e][l] + bfc[m] ----
#pragma unroll
    for (int e = 0; e < EPW; ++e) {
#pragma unroll
        for (int m = 0; m < 6; ++m) {
            float p = smf[OFF_WFC + m * H2P + lane] * h2v[e];
#pragma unroll
            for (int off = 16; off > 0; off >>= 1)
                p += __shfl_xor_sync(FULLMASK, p, off);
            if (lane == 0)
                out[(size_t)(ebase + e) * 6 + m] = p + smf[OFF_BFC + m];
        }
    }
}

extern "C" void kernel_launch(void* const* d_in, const int* in_sizes, int n_in,
                              void* d_out, int out_size) {
    (void)in_sizes; (void)n_in; (void)out_size;
    const float* x    = (const float*)d_in[0];
    const float* Wih1 = (const float*)d_in[1];
    const float* Whh1 = (const float*)d_in[2];
    const float* bih1 = (const float*)d_in[3];
    const float* bhh1 = (const float*)d_in[4];
    const float* Wih2 = (const float*)d_in[5];
    const float* Whh2 = (const float*)d_in[6];
    const float* bih2 = (const float*)d_in[7];
    const float* bhh2 = (const float*)d_in[8];
    const float* Wfc  = (const float*)d_in[9];
    const float* bfc  = (const float*)d_in[10];
    float* out = (float*)d_out;

    static bool attr_set = false;
    if (!attr_set) {
        cudaFuncSetAttribute(lstm2_kernel,
                             cudaFuncAttributeMaxDynamicSharedMemorySize, SMEM_BYTES);
        attr_set = true;
    }
    const int epc = NWARP * EPW;               // 28 elements per CTA
    const int grid = (BB + epc - 1) / epc;     // 147
    lstm2_kernel<<<grid, NTHR, SMEM_BYTES>>>(x, Wih1, Whh1, bih1, bhh1,
                                             Wih2, Whh2, bih2, bhh2, Wfc, bfc, out);
}